// round 17
// baseline (speedup 1.0000x reference)
#include <cuda_runtime.h>
#include <cuda_fp16.h>
#include <math.h>

#define BATCH 65536
#define NQ 8
#define FULLM 0xffffffffu

typedef unsigned char u8;
typedef unsigned int u32;
typedef unsigned long long ull;

// ================= compile-time GF(2) algebra for CNOT ladder =================
struct M8 { u8 c[8]; };

__host__ __device__ constexpr u8 mv(const M8& m, u8 x) {
    u8 y = 0;
    for (int j = 0; j < 8; j++) if ((x >> j) & 1) y = (u8)(y ^ m.c[j]);
    return y;
}
__host__ __device__ constexpr M8 mm(const M8& a, const M8& b) {
    M8 r{}; for (int j = 0; j < 8; j++) r.c[j] = mv(a, b.c[j]); return r;
}
__host__ __device__ constexpr M8 ident() {
    M8 m{}; for (int j = 0; j < 8; j++) m.c[j] = (u8)(1u << j); return m;
}
__host__ __device__ constexpr M8 ladder() {
    M8 L = ident();
    for (int i = 0; i < 8; i++)
        for (int j = i + 1; j < 8; j++) {
            int cb = 7 - i, tb = 7 - j;
            M8 P = ident();
            P.c[cb] = (u8)((1u << cb) | (1u << tb));
            L = mm(L, P);
        }
    return L;
}
__host__ __device__ constexpr M8 minv(const M8& a) {
    u8 row[8] = {}, inv[8] = {};
    for (int i = 0; i < 8; i++) inv[i] = (u8)(1u << i);
    for (int i = 0; i < 8; i++)
        for (int j = 0; j < 8; j++)
            if ((a.c[j] >> i) & 1) row[i] = (u8)(row[i] | (1u << j));
    for (int col = 0; col < 8; col++) {
        int piv = col;
        while (!((row[piv] >> col) & 1)) piv++;
        u8 t = row[col]; row[col] = row[piv]; row[piv] = t;
        t = inv[col]; inv[col] = inv[piv]; inv[piv] = t;
        for (int i = 0; i < 8; i++)
            if (i != col && ((row[i] >> col) & 1)) { row[i] = (u8)(row[i] ^ row[col]); inv[i] = (u8)(inv[i] ^ inv[col]); }
    }
    M8 r{};
    for (int i = 0; i < 8; i++)
        for (int j = 0; j < 8; j++)
            if ((inv[i] >> j) & 1) r.c[j] = (u8)(r.c[j] | (1u << i));
    return r;
}
__host__ __device__ constexpr int par8(int x) { x ^= x >> 4; x ^= x >> 2; x ^= x >> 1; return x & 1; }

struct Masks {
    u8 v[3][8];
    u8 r[3][8];
    u8 rf[8];
};
__host__ __device__ constexpr Masks make_masks() {
    Masks mk{};
    M8 L = ladder();
    M8 C = ident();
    for (int l = 0; l < 3; l++) {
        M8 Ci = minv(C);
        for (int q = 0; q < 8; q++) {
            int B = 7 - q;
            mk.v[l][q] = mv(C, (u8)(1u << B));
            u8 rr = 0;
            for (int j = 0; j < 8; j++) if ((Ci.c[j] >> B) & 1) rr = (u8)(rr | (1u << j));
            mk.r[l][q] = rr;
        }
        C = mm(C, L);
    }
    M8 Cf = minv(C);
    for (int q = 0; q < 8; q++) {
        int B = 7 - q;
        u8 rr = 0;
        for (int j = 0; j < 8; j++) if ((Cf.c[j] >> B) & 1) rr = (u8)(rr | (1u << j));
        mk.rf[q] = rr;
    }
    return mk;
}
constexpr Masks MK = make_masks();

__host__ __device__ constexpr bool masks_ok() {
    constexpr Masks mk = make_masks();
    M8 L = ladder();
    M8 C = ident();
    for (int l = 0; l < 3; l++) {
        M8 Ci = minv(C);
        M8 P = mm(C, Ci);
        for (int j = 0; j < 8; j++) if (P.c[j] != (u8)(1u << j)) return false;
        for (int q = 0; q < 8; q++)
            if (par8(mk.v[l][q] & mk.r[l][q]) != 1) return false;
        C = mm(C, L);
    }
    return true;
}
static_assert(masks_ok(), "GF(2) mask algebra broken");

// sign LUT: SIG.v[j] bit q = parity(j & rf[q])
struct SigT { u8 v[256]; };
__host__ __device__ constexpr SigT make_sig() {
    SigT s{};
    Masks mk = make_masks();
    for (int j = 0; j < 256; j++) {
        u8 b = 0;
        for (int q = 0; q < 8; q++) if (par8(j & mk.rf[q])) b = (u8)(b | (1u << q));
        s.v[j] = b;
    }
    return s;
}
__constant__ SigT SIGC = make_sig();

// ================= f32x2 / smem helpers =================
__device__ __forceinline__ ull fpk(float lo, float hi) {
    ull r; asm("mov.b64 %0, {%1,%2};" : "=l"(r) : "f"(lo), "f"(hi)); return r;
}
__device__ __forceinline__ void funpk(ull v, float& lo, float& hi) {
    asm("mov.b64 {%0,%1}, %2;" : "=f"(lo), "=f"(hi) : "l"(v));
}
__device__ __forceinline__ ull mul2(ull a, ull b) {
    ull d; asm("mul.rn.f32x2 %0, %1, %2;" : "=l"(d) : "l"(a), "l"(b)); return d;
}
__device__ __forceinline__ ull fma2(ull a, ull b, ull c) {
    ull d; asm("fma.rn.f32x2 %0, %1, %2, %3;" : "=l"(d) : "l"(a), "l"(b), "l"(c)); return d;
}
__device__ __forceinline__ ull add2(ull a, ull b) {
    ull d; asm("add.rn.f32x2 %0, %1, %2;" : "=l"(d) : "l"(a), "l"(b)); return d;
}
__device__ __forceinline__ float psum(ull v) {
    float lo, hi; funpk(v, lo, hi); return lo + hi;
}
__device__ __forceinline__ ull dot4(ull acc, float4 w, float4 h) {
    acc = fma2(fpk(w.x, w.y), fpk(h.x, h.y), acc);
    acc = fma2(fpk(w.z, w.w), fpk(h.z, h.w), acc);
    return acc;
}
__device__ __forceinline__ ull shfl_xor_u64(ull v, int m) {
    u32 lo = (u32)v, hi = (u32)(v >> 32);
    lo = __shfl_xor_sync(FULLM, lo, m);
    hi = __shfl_xor_sync(FULLM, hi, m);
    return ((ull)hi << 32) | lo;
}
__device__ __forceinline__ void ldsm_x4(u32& r0, u32& r1, u32& r2, u32& r3, u32 addr) {
    asm volatile("ldmatrix.sync.aligned.m8n8.x4.shared.b16 {%0,%1,%2,%3}, [%4];"
                 : "=r"(r0), "=r"(r1), "=r"(r2), "=r"(r3) : "r"(addr));
}

struct GatePack { ull AR, AIp, AIn, BRp, BRn, BIp, BIn, pad; };

// ================= device scratch =================
__device__ float    d_W1f[128 * 16];
__device__ float    d_b1f[128];
__device__ float    d_W2T[128 * 64];   // BN-folded W2, TRANSPOSED [k][o]
__device__ float    d_b2f[64];
__device__ float    d_W4f[32 * 8];
__device__ float    d_b4f[32];
__device__ GatePack d_qgp[24];
__device__ uint4    d_BhR[512 * 32];   // B fp16 [512 n][256 k] (256KB)

// ================= precompute =================
__global__ void precompute_kernel(
    const float* W1, const float* b1, const float* g1, const float* bt1, const float* m1, const float* v1,
    const float* W2, const float* b2, const float* g2, const float* bt2, const float* m2, const float* v2,
    const float* W4, const float* b4, const float* g4, const float* bt4, const float* m4, const float* v4,
    const float* qw)
{
    int t = threadIdx.x;  // 128
    if (t < 128) {
        float a = g1[t] * rsqrtf(v1[t] + 1e-5f);
        for (int k = 0; k < 16; k++) d_W1f[t * 16 + k] = W1[t * 16 + k] * a;
        d_b1f[t] = (b1[t] - m1[t]) * a + bt1[t];
    }
    if (t < 64) {
        float a = g2[t] * rsqrtf(v2[t] + 1e-5f);
        for (int k = 0; k < 128; k++) d_W2T[k * 64 + t] = W2[t * 128 + k] * a;
        d_b2f[t] = (b2[t] - m2[t]) * a + bt2[t];
    }
    if (t < 32) {
        float a = g4[t] * rsqrtf(v4[t] + 1e-5f);
        for (int k = 0; k < 8; k++) d_W4f[t * 8 + k] = W4[t * 8 + k] * a;
        d_b4f[t] = (b4[t] - m4[t]) * a + bt4[t];
    }
    if (t < 24) {
        float sx, cx, sy, cy, sz, cz;
        sincosf(0.5f * qw[t * 3 + 0], &sx, &cx);
        sincosf(0.5f * qw[t * 3 + 1], &sy, &cy);
        sincosf(0.5f * qw[t * 3 + 2], &sz, &cz);
        float cycx = cy * cx, sysx = sy * sx, sycx = sy * cx, cysx = cy * sx;
        float ar  = cz * cycx - sz * sysx;
        float ai0 = -(cz * sysx + sz * cycx);
        float br0 = cz * sycx - sz * cysx;
        float bi  = -(cz * cysx + sz * sycx);
        Masks mk = make_masks();
        int l = t >> 3, q = t & 7;
        int rr = mk.r[l][q] & 7;
        float tau = (rr & 1) ? -1.f : 1.f;
        GatePack g;
        g.AR  = fpk(ar, ar);
        g.AIp = fpk(ai0,  tau * ai0);
        g.AIn = fpk(-ai0, -tau * ai0);
        g.BRp = fpk(br0,  tau * br0);
        g.BRn = fpk(-br0, -tau * br0);
        g.BIp = fpk(bi, bi);
        g.BIn = fpk(-bi, -bi);
        g.pad = 0;
        d_qgp[t] = g;
    }
}

// ================= packed gate machinery (verified) =================
template<int X> struct Par {
    static constexpr int val =
        ((X >> 7) ^ (X >> 6) ^ (X >> 5) ^ (X >> 4) ^ (X >> 3) ^ (X >> 2) ^ (X >> 1) ^ X) & 1;
};

template<int V, int R>
__device__ __forceinline__ void gate2(ull X[4], ull Y[4], const GatePack* gp, int lane)
{
    static_assert(Par<V & R>::val == 1, "pair/branch masks inconsistent");
    constexpr int vl = (V >> 3) & 31, vr = V & 7;
    constexpr int rl = (R >> 3) & 31, rr = R & 7;

    ull AR  = gp->AR;
    ull BIp = gp->BIp;
    ull BIn = gp->BIn;
    bool lp = (__popc(lane & rl) & 1) != 0;
    ull AIpf = lp ? gp->AIn : gp->AIp;
    ull AInf = lp ? gp->AIp : gp->AIn;
    ull BRpf = lp ? gp->BRn : gp->BRp;
    ull BRnf = lp ? gp->BRp : gp->BRn;

    ull PX[4], PY[4];
    #pragma unroll
    for (int k = 0; k < 4; k++) {
        const int kp = k ^ (vr >> 1);
        if constexpr ((vr & 1) != 0) {
            float xlo, xhi, ylo, yhi;
            funpk(X[kp], xlo, xhi);
            funpk(Y[kp], ylo, yhi);
            if constexpr (vl != 0) {
                xlo = __shfl_xor_sync(FULLM, xlo, vl);
                xhi = __shfl_xor_sync(FULLM, xhi, vl);
                ylo = __shfl_xor_sync(FULLM, ylo, vl);
                yhi = __shfl_xor_sync(FULLM, yhi, vl);
            }
            PX[k] = fpk(xhi, xlo);
            PY[k] = fpk(yhi, ylo);
        } else {
            if constexpr (vl != 0) {
                PX[k] = __shfl_xor_sync(FULLM, X[kp], vl);
                PY[k] = __shfl_xor_sync(FULLM, Y[kp], vl);
            } else {
                PX[k] = X[kp];
                PY[k] = Y[kp];
            }
        }
    }
    #pragma unroll
    for (int k = 0; k < 4; k++) {
        const bool s0 = ((__popc((2 * k) & rr) & 1) != 0);
        ull AIx = s0 ? AIpf : AInf;
        ull AIy = s0 ? AInf : AIpf;
        ull BR  = s0 ? BRnf : BRpf;
        ull t1 = mul2(X[k], AR);
        t1 = fma2(Y[k],  AIx, t1);
        t1 = fma2(PX[k], BR,  t1);
        t1 = fma2(PY[k], BIn, t1);
        ull t2 = mul2(Y[k], AR);
        t2 = fma2(X[k],  AIy, t2);
        t2 = fma2(PY[k], BR,  t2);
        t2 = fma2(PX[k], BIp, t2);
        X[k] = t1; Y[k] = t2;
    }
}

template<int L, int Q>
__device__ __forceinline__ void gate(ull X[4], ull Y[4], const GatePack* gs, int lane)
{
    gate2<MK.v[L][Q], MK.r[L][Q]>(X, Y, gs + (L * 8 + Q), lane);
}

// ================= build U: warp k simulates basis k; B stored [n=512][k=256] fp16 =================
__global__ void __launch_bounds__(256) build_U_kernel()
{
    __shared__ GatePack gs[24];
    __shared__ half Bst[512][8];
    int t = threadIdx.x;
    if (t < 192) ((ull*)gs)[t] = ((const ull*)d_qgp)[t];
    __syncthreads();

    int w = t >> 5;
    int k = blockIdx.x * 8 + w;
    int lane = t & 31;

    ull X[4], Y[4];
    #pragma unroll
    for (int p = 0; p < 4; p++) {
        int j0 = lane * 8 + 2 * p, j1 = j0 + 1;
        X[p] = fpk(j0 == k ? 1.f : 0.f, j1 == k ? 1.f : 0.f);
        Y[p] = fpk(0.f, 0.f);
    }

    gate<0,0>(X, Y, gs, lane); gate<0,1>(X, Y, gs, lane); gate<0,2>(X, Y, gs, lane); gate<0,3>(X, Y, gs, lane);
    gate<0,4>(X, Y, gs, lane); gate<0,5>(X, Y, gs, lane); gate<0,6>(X, Y, gs, lane); gate<0,7>(X, Y, gs, lane);
    gate<1,0>(X, Y, gs, lane); gate<1,1>(X, Y, gs, lane); gate<1,2>(X, Y, gs, lane); gate<1,3>(X, Y, gs, lane);
    gate<1,4>(X, Y, gs, lane); gate<1,5>(X, Y, gs, lane); gate<1,6>(X, Y, gs, lane); gate<1,7>(X, Y, gs, lane);
    gate<2,0>(X, Y, gs, lane); gate<2,1>(X, Y, gs, lane); gate<2,2>(X, Y, gs, lane); gate<2,3>(X, Y, gs, lane);
    gate<2,4>(X, Y, gs, lane); gate<2,5>(X, Y, gs, lane); gate<2,6>(X, Y, gs, lane); gate<2,7>(X, Y, gs, lane);

    #pragma unroll
    for (int p = 0; p < 4; p++) {
        float x0, x1, y0, y1;
        funpk(X[p], x0, x1);
        funpk(Y[p], y0, y1);
        int j0 = lane * 8 + 2 * p, j1 = j0 + 1;
        Bst[2 * j0][w]     = __float2half_rn(x0);
        Bst[2 * j0 + 1][w] = __float2half_rn(y0);
        Bst[2 * j1][w]     = __float2half_rn(x1);
        Bst[2 * j1 + 1][w] = __float2half_rn(y1);
    }
    __syncthreads();

    half* Bh = (half*)d_BhR;
    for (int i = t; i < 512; i += 256)
        *(uint4*)&Bh[i * 256 + blockIdx.x * 8] = *(uint4*)&Bst[i][0];
}

// ================= fused kernel: front MLP + A build + GEMM + tail =================
#define AS_STR 264
#define BS_STR 264
#define GSMEM (128 * AS_STR * 2 + 64 * BS_STR * 2 + 128 * 8 * 4)

__global__ void __launch_bounds__(256, 2) gemm_kernel(
    const float* __restrict__ xglob,
    const float* __restrict__ W3, const float* __restrict__ b3,
    const float* __restrict__ W5, const float* __restrict__ b5,
    const float* __restrict__ W6, const float* __restrict__ b6,
    float* __restrict__ out)
{
    extern __shared__ char smem[];
    half*  As   = (half*)smem;                          // [128][264]
    half*  Bs   = As + 128 * AS_STR;                    // [64][264]
    float* outs = (float*)(Bs + 64 * BS_STR);           // [128*8]
    __shared__ float w4s[32 * 8], b4s[32], w5s[16 * 32], b5s[16], w6s[16], b6s[1];

    // --- staging region (front of pool; overwritten by As after front-phase) ---
    float* stW1  = (float*)smem;          // 2048 floats
    float* stW2T = stW1 + 2048;           // 8192 floats [k][o]
    float* stW3  = stW2T + 8192;          // 512 floats
    float* stB1  = stW3 + 512;            // 128
    float* stB2  = stB1 + 128;            // 64
    float* stB3  = stB2 + 64;             // 8

    int t = threadIdx.x;
    int warp = t >> 5, lane = t & 31;
    int gid = lane >> 2, tig = lane & 3;
    int wm = warp & 3, wn = warp >> 2;
    int eb = blockIdx.x * 128;

    const half* Bh = (const half*)d_BhR;

    // ---- stage tail weights (static smem) + front weights (dynamic pool) ----
    w4s[t] = d_W4f[t];
    if (t < 32) b4s[t] = d_b4f[t];
    for (int i = t; i < 16 * 32; i += 256) w5s[i] = W5[i];
    if (t < 16) { b5s[t] = b5[t]; w6s[t] = W6[t]; }
    if (t == 0) b6s[0] = b6[0];

    for (int i = t; i < 512; i += 256)  ((float4*)stW1)[i]  = ((const float4*)d_W1f)[i];
    for (int i = t; i < 2048; i += 256) ((float4*)stW2T)[i] = ((const float4*)d_W2T)[i];
    if (t < 128) ((float4*)stW3)[t] = ((const float4*)W3)[t];
    if (t < 128) stB1[t] = d_b1f[t];
    if (t < 64)  stB2[t] = d_b2f[t];
    if (t < 8)   stB3[t] = b3[t];
    for (int i = t; i < 128 * 8; i += 256) outs[i] = 0.f;

    // x row for this thread's pair-row (4 float4)
    int rrow = t >> 1, h = t & 1;
    const float4* xg = ((const float4*)xglob) + (ull)(eb + rrow) * 4;
    float4 xv0 = xg[0], xv1 = xg[1], xv2 = xg[2], xv3 = xg[3];
    __syncthreads();

    // ================== front MLP (register resident, pair-split over k) ==================
    float2 cs[8];
    {
        const float4* W1v  = (const float4*)stW1;
        const float4* W2Tv = (const float4*)stW2T;

        ull acc2[32];
        #pragma unroll
        for (int o2 = 0; o2 < 32; o2++) acc2[o2] = fpk(0.f, 0.f);

        // layer1 neuron k (own half) -> immediately accumulate into layer2 packed accs
        #pragma unroll 4
        for (int kk = 0; kk < 64; kk++) {
            int k = h * 64 + kk;
            ull ap = fpk(0.f, 0.f);
            ap = dot4(ap, W1v[k * 4 + 0], xv0);
            ap = dot4(ap, W1v[k * 4 + 1], xv1);
            ap = dot4(ap, W1v[k * 4 + 2], xv2);
            ap = dot4(ap, W1v[k * 4 + 3], xv3);
            float h1k = fmaxf(stB1[k] + psum(ap), 0.f);
            ull hp = fpk(h1k, h1k);
            #pragma unroll
            for (int o4 = 0; o4 < 16; o4++) {
                float4 wq = W2Tv[k * 16 + o4];
                acc2[2 * o4]     = fma2(hp, fpk(wq.x, wq.y), acc2[2 * o4]);
                acc2[2 * o4 + 1] = fma2(hp, fpk(wq.z, wq.w), acc2[2 * o4 + 1]);
            }
        }

        // merge k-halves with partner thread, ReLU -> h2[64] (identical in both threads)
        float h2[64];
        #pragma unroll
        for (int o2 = 0; o2 < 32; o2++) {
            ull v = add2(acc2[o2], shfl_xor_u64(acc2[o2], 1));
            float lo, hi; funpk(v, lo, hi);
            h2[2 * o2]     = fmaxf(stB2[2 * o2] + lo, 0.f);
            h2[2 * o2 + 1] = fmaxf(stB2[2 * o2 + 1] + hi, 0.f);
        }

        // layer3 + tanh + sincos
        const float4* W3v = (const float4*)stW3;
        #pragma unroll
        for (int o = 0; o < 8; o++) {
            ull ap = fpk(0.f, 0.f);
            #pragma unroll
            for (int k4 = 0; k4 < 16; k4++) {
                float4 w = W3v[o * 16 + k4];
                ap = fma2(fpk(w.x, w.y), fpk(h2[4 * k4], h2[4 * k4 + 1]), ap);
                ap = fma2(fpk(w.z, w.w), fpk(h2[4 * k4 + 2], h2[4 * k4 + 3]), ap);
            }
            float pre = tanhf(stB3[o] + psum(ap));
            float sc, cc;
            __sincosf(0.5f * pre, &sc, &cc);
            cs[o] = make_float2(cc, sc);
        }
    }
    __syncthreads();   // all threads done reading staging; As writes may begin

    // ================== build A tile in smem (fp16) ==================
    {
        #pragma unroll
        for (int hi8 = 0; hi8 < 8; hi8++) {
            int hi = h * 8 + hi8;
            float fhi = 1.f;
            fhi *= (hi & 8) ? -cs[0].y : cs[0].x;
            fhi *= (hi & 4) ? -cs[1].y : cs[1].x;
            fhi *= (hi & 2) ? -cs[2].y : cs[2].x;
            fhi *= (hi & 1) ? -cs[3].y : cs[3].x;
            float A1[2], A2[4], A3[8], A4[16];
            A1[0] = fhi * cs[4].x;  A1[1] = -fhi * cs[4].y;
            #pragma unroll
            for (int i = 0; i < 4; i++)  A2[i] = A1[i >> 1] * ((i & 1) ? -cs[5].y : cs[5].x);
            #pragma unroll
            for (int i = 0; i < 8; i++)  A3[i] = A2[i >> 1] * ((i & 1) ? -cs[6].y : cs[6].x);
            #pragma unroll
            for (int i = 0; i < 16; i++) A4[i] = A3[i >> 1] * ((i & 1) ? -cs[7].y : cs[7].x);
            half2 h2v[8];
            #pragma unroll
            for (int i = 0; i < 8; i++) h2v[i] = __floats2half2_rn(A4[2 * i], A4[2 * i + 1]);
            uint4* dst = (uint4*)&As[rrow * AS_STR + hi * 16];
            dst[0] = *(uint4*)&h2v[0];
            dst[1] = *(uint4*)&h2v[4];
        }
    }

    // ---- precompute per-lane ldmatrix base addresses ----
    int g = lane >> 3, lr = lane & 7;
    u32 As_base = (u32)__cvta_generic_to_shared(As);
    u32 Bs_base = (u32)__cvta_generic_to_shared(Bs);
    u32 a_addr[2], b_addr[2];
    #pragma unroll
    for (int mt = 0; mt < 2; mt++) {
        int row = wm * 32 + mt * 16 + lr + (g & 1) * 8;
        a_addr[mt] = As_base + (u32)(row * AS_STR + (g >> 1) * 8) * 2;
    }
    #pragma unroll
    for (int p = 0; p < 2; p++) {
        int col = wn * 32 + p * 16 + lr + (g >> 1) * 8;
        b_addr[p] = Bs_base + (u32)(col * BS_STR + (g & 1) * 8) * 2;
    }

    float outp[4][8];
    #pragma unroll
    for (int i = 0; i < 4; i++)
        #pragma unroll
        for (int q = 0; q < 8; q++) outp[i][q] = 0.f;

    for (int ntile = 0; ntile < 8; ntile++) {
        __syncthreads();
        for (int c = t; c < 2048; c += 256) {
            int n = c >> 5, k8 = c & 31;
            *(float4*)&Bs[n * BS_STR + k8 * 8] =
                *(const float4*)&Bh[(ntile * 64 + n) * 256 + k8 * 8];
        }
        __syncthreads();

        float acc[2][4][4];
        #pragma unroll
        for (int mt = 0; mt < 2; mt++)
            #pragma unroll
            for (int nf = 0; nf < 4; nf++)
                #pragma unroll
                for (int rr = 0; rr < 4; rr++) acc[mt][nf][rr] = 0.f;

        #pragma unroll
        for (int ks = 0; ks < 16; ks++) {
            u32 koff = (u32)(ks * 16) * 2;
            u32 a[2][4];
            ldsm_x4(a[0][0], a[0][1], a[0][2], a[0][3], a_addr[0] + koff);
            ldsm_x4(a[1][0], a[1][1], a[1][2], a[1][3], a_addr[1] + koff);
            u32 b[4][2];
            ldsm_x4(b[0][0], b[0][1], b[1][0], b[1][1], b_addr[0] + koff);
            ldsm_x4(b[2][0], b[2][1], b[3][0], b[3][1], b_addr[1] + koff);
            #pragma unroll
            for (int mt = 0; mt < 2; mt++)
                #pragma unroll
                for (int nf = 0; nf < 4; nf++) {
                    asm volatile(
                        "mma.sync.aligned.m16n8k16.row.col.f32.f16.f16.f32 "
                        "{%0,%1,%2,%3}, {%4,%5,%6,%7}, {%8,%9}, {%0,%1,%2,%3};"
                        : "+f"(acc[mt][nf][0]), "+f"(acc[mt][nf][1]),
                          "+f"(acc[mt][nf][2]), "+f"(acc[mt][nf][3])
                        : "r"(a[mt][0]), "r"(a[mt][1]), "r"(a[mt][2]), "r"(a[mt][3]),
                          "r"(b[nf][0]), "r"(b[nf][1]));
                }
        }

        // epilogue: cols (2j, 2j+1) = (Re, Im) in (c0,c1)/(c2,c3)
        #pragma unroll
        for (int mt = 0; mt < 2; mt++)
            #pragma unroll
            for (int nf = 0; nf < 4; nf++) {
                int j = ntile * 32 + wn * 16 + nf * 4 + tig;
                u8 sb = SIGC.v[j];
                float p0 = acc[mt][nf][0] * acc[mt][nf][0] + acc[mt][nf][1] * acc[mt][nf][1];
                float p1 = acc[mt][nf][2] * acc[mt][nf][2] + acc[mt][nf][3] * acc[mt][nf][3];
                #pragma unroll
                for (int q = 0; q < 8; q++) {
                    float s0 = ((sb >> q) & 1) ? -p0 : p0;
                    float s1 = ((sb >> q) & 1) ? -p1 : p1;
                    outp[mt * 2 + 0][q] += s0;
                    outp[mt * 2 + 1][q] += s1;
                }
            }
    }

    #pragma unroll
    for (int idx = 0; idx < 4; idx++) {
        int row = wm * 32 + idx * 8 + gid;
        #pragma unroll
        for (int q = 0; q < 8; q++)
            atomicAdd(&outs[row * 8 + q], outp[idx][q]);
    }
    __syncthreads();

    // ---- fused tail MLP: one thread per row ----
    if (t < 128) {
        float q[8];
        #pragma unroll
        for (int i = 0; i < 8; i++) q[i] = outs[t * 8 + i];

        float h5[16];
        #pragma unroll
        for (int j = 0; j < 16; j++) h5[j] = b5s[j];
        #pragma unroll
        for (int o = 0; o < 32; o++) {
            float a = b4s[o];
            #pragma unroll
            for (int k = 0; k < 8; k++) a += w4s[o * 8 + k] * q[k];
            a = fmaxf(a, 0.f);
            #pragma unroll
            for (int j = 0; j < 16; j++) h5[j] += w5s[j * 32 + o] * a;
        }
        float o6 = b6s[0];
        #pragma unroll
        for (int j = 0; j < 16; j++) o6 += fmaxf(h5[j], 0.f) * w6s[j];
        out[eb + t] = o6;
    }
}

// ================= launch =================
extern "C" void kernel_launch(void* const* d_in, const int* in_sizes, int n_in,
                              void* d_out, int out_size)
{
    const float* x   = (const float*)d_in[0];
    const float* W1  = (const float*)d_in[1];
    const float* b1  = (const float*)d_in[2];
    const float* g1  = (const float*)d_in[3];
    const float* bt1 = (const float*)d_in[4];
    const float* m1  = (const float*)d_in[5];
    const float* v1  = (const float*)d_in[6];
    const float* W2  = (const float*)d_in[7];
    const float* b2  = (const float*)d_in[8];
    const float* g2  = (const float*)d_in[9];
    const float* bt2 = (const float*)d_in[10];
    const float* m2  = (const float*)d_in[11];
    const float* v2  = (const float*)d_in[12];
    const float* W3  = (const float*)d_in[13];
    const float* b3  = (const float*)d_in[14];
    const float* qw  = (const float*)d_in[15];
    const float* W4  = (const float*)d_in[16];
    const float* b4  = (const float*)d_in[17];
    const float* g4  = (const float*)d_in[18];
    const float* bt4 = (const float*)d_in[19];
    const float* m4  = (const float*)d_in[20];
    const float* v4_ = (const float*)d_in[21];
    const float* W5  = (const float*)d_in[22];
    const float* b5  = (const float*)d_in[23];
    const float* W6  = (const float*)d_in[24];
    const float* b6  = (const float*)d_in[25];

    static bool attr_set = false;
    if (!attr_set) {
        cudaFuncSetAttribute(gemm_kernel, cudaFuncAttributeMaxDynamicSharedMemorySize, GSMEM);
        attr_set = true;
    }

    precompute_kernel<<<1, 128>>>(W1, b1, g1, bt1, m1, v1,
                                  W2, b2, g2, bt2, m2, v2,
                                  W4, b4, g4, bt4, m4, v4_, qw);
    build_U_kernel<<<32, 256>>>();
    gemm_kernel<<<BATCH / 128, 256, GSMEM>>>(x, W3, b3, W5, b5, W6, b6, (float*)d_out);
}